// round 13
// baseline (speedup 1.0000x reference)
#include <cuda_runtime.h>
#include <cuda_fp16.h>
#include <cstdint>
#include <math.h>

// fp16 tile scratch (4MB total): ey[n][h][p], exv[n][c][w][p]
__device__ __half g_ey[4 * 128 * 1024];
__device__ __half g_bv[12 * 128 * 1024];

static __device__ __forceinline__ uint32_t s2u(const void* p) {
    uint32_t a;
    asm("{ .reg .u64 t; cvta.to.shared.u64 t, %1; cvt.u32.u64 %0, t; }" : "=r"(a) : "l"(p));
    return a;
}
static __device__ __forceinline__ float fast_exp2(float x) {
    float y; asm("ex2.approx.ftz.f32 %0, %1;" : "=f"(y) : "f"(x)); return y;
}
static __device__ __forceinline__ uint32_t pack_h2(float lo, float hi) {
    uint32_t u;
    asm("cvt.rn.f16x2.f32 %0, %1, %2;" : "=r"(u) : "f"(hi), "f"(lo));  // d.lo = %2
    return u;
}
static __device__ __forceinline__ uint32_t hmul2(uint32_t a, uint32_t b) {
    uint32_t d;
    asm("mul.rn.f16x2 %0, %1, %2;" : "=r"(d) : "r"(a), "r"(b));
    return d;
}
static __device__ __forceinline__ uint32_t sw128(uint32_t off) {
    return off ^ ((off >> 3) & 0x70);
}
static __device__ __forceinline__ void ldsm_x4(uint32_t addr, uint32_t& r0, uint32_t& r1,
                                               uint32_t& r2, uint32_t& r3) {
    asm volatile("ldmatrix.sync.aligned.m8n8.x4.shared.b16 {%0,%1,%2,%3}, [%4];"
                 : "=r"(r0), "=r"(r1), "=r"(r2), "=r"(r3) : "r"(addr));
}
static __device__ __forceinline__ void mma16816(float* c, uint32_t a0, uint32_t a1,
                                                uint32_t a2, uint32_t a3,
                                                uint32_t b0, uint32_t b1) {
    asm volatile(
        "mma.sync.aligned.m16n8k16.row.col.f32.f16.f16.f32 "
        "{%0,%1,%2,%3}, {%4,%5,%6,%7}, {%8,%9}, {%0,%1,%2,%3};"
        : "+f"(c[0]), "+f"(c[1]), "+f"(c[2]), "+f"(c[3])
        : "r"(a0), "r"(a1), "r"(a2), "r"(a3), "r"(b0), "r"(b1));
}
static __device__ __forceinline__ void cp_async16(uint32_t dst, const void* src) {
    asm volatile("cp.async.cg.shared.global [%0], [%1], 16;"
                 :: "r"(dst), "l"(src) : "memory");
}

// ============================================================================
// Phase 1: tile factory. 131072 independent 8-point tasks, exps computed once.
//   gid < 65536 : exv task (n, w, pg)  -> g_bv (3 channels)
//   else        : ey  task (n, h, pg)  -> g_ey
// ============================================================================
__global__ void __launch_bounds__(256)
splat2d_tiles(const float* __restrict__ coords,   // [N,1024,2]
              const float* __restrict__ values,   // [N,1024,3]
              const float* __restrict__ sigma) {  // [N,1]
    const int gid   = blockIdx.x * 256 + threadIdx.x;
    const bool isbv = gid < 65536;
    const int t  = isbv ? gid : gid - 65536;
    const int pg = t & 127;                 // 8-point group
    const int rw = (t >> 7) & 127;          // w (bv) or h (ey)
    const int n  = t >> 14;

    const float a_ = sqrtf(0.72134752044448169f) / sigma[n];  // sqrt(log2e/2)/sigma
    const float ar = a_ * (float)rw;

    const float4* cp4 = (const float4*)(coords + (size_t)n * 2048) + pg * 4;
    const float4 q0 = cp4[0], q1 = cp4[1], q2 = cp4[2], q3 = cp4[3];

    if (isbv) {
        const float px[8] = {q0.x, q0.z, q1.x, q1.z, q2.x, q2.z, q3.x, q3.z};
        float e[8];
        #pragma unroll
        for (int i = 0; i < 8; ++i) {
            const float d = fmaf(a_, -px[i], ar);   // a*(w - px)
            e[i] = fast_exp2(-d * d);
        }
        uint32_t eh[4];
        #pragma unroll
        for (int q = 0; q < 4; ++q) eh[q] = pack_h2(e[2 * q], e[2 * q + 1]);

        const float4* vp4 = (const float4*)(values + (size_t)n * 3072 + pg * 24);
        float vf[24];
        #pragma unroll
        for (int j = 0; j < 6; ++j) {
            const float4 v = vp4[j];
            vf[4 * j] = v.x; vf[4 * j + 1] = v.y; vf[4 * j + 2] = v.z; vf[4 * j + 3] = v.w;
        }
        #pragma unroll
        for (int c = 0; c < 3; ++c) {
            uint32_t m[4];
            #pragma unroll
            for (int q = 0; q < 4; ++q)
                m[q] = hmul2(eh[q], pack_h2(vf[6 * q + c], vf[6 * q + 3 + c]));
            ((uint4*)g_bv)[(size_t)((n * 3 + c) * 128 + rw) * 128 + pg] =
                make_uint4(m[0], m[1], m[2], m[3]);
        }
    } else {
        const float py[8] = {q0.y, q0.w, q1.y, q1.w, q2.y, q2.w, q3.y, q3.w};
        float e[8];
        #pragma unroll
        for (int i = 0; i < 8; ++i) {
            const float d = fmaf(a_, -py[i], ar);   // a*(h - py)
            e[i] = fast_exp2(-d * d);
        }
        ((uint4*)g_ey)[(size_t)(n * 128 + rw) * 128 + pg] =
            make_uint4(pack_h2(e[0], e[1]), pack_h2(e[2], e[3]),
                       pack_h2(e[4], e[5]), pack_h2(e[6], e[7]));
    }
}

// ============================================================================
// Phase 2: pure GEMM, K=1024, direct store. CTA = (32h x 64w, c, n), grid 96.
// 8 K-chunks of 128p; 3-stage cp.async pipeline; stage = A 8KB + B 16KB.
// ============================================================================
#define STAGE_B 24576
#define SMEM2   (3 * STAGE_B)

__global__ void __launch_bounds__(128)
splat2d_gemm(float* __restrict__ out) {
    extern __shared__ __align__(1024) char smem[];
    const uint32_t sbase = s2u(smem);
    const int tid = threadIdx.x;
    const int ht  = blockIdx.x >> 1;        // 32-row h-tile
    const int wh  = blockIdx.x & 1;         // 64-col w-half
    const int c   = blockIdx.y;
    const int n   = blockIdx.z;
    const int h0  = ht * 32;
    const int w0  = wh * 64;

    const char* gA = (const char*)g_ey + (size_t)(n * 128 + h0) * 2048;
    const char* gB = (const char*)g_bv + (size_t)((n * 3 + c) * 128 + w0) * 2048;

    auto load_chunk = [&](int ck, int stage) {
        const uint32_t sb = sbase + stage * STAGE_B;
        #pragma unroll
        for (int k = 0; k < 4; ++k) {       // A: 32 rows x 16 granules
            const int id = tid + k * 128;
            const int r = id >> 4, g = id & 15;
            cp_async16(sb + (g >> 3) * 4096 + sw128((uint32_t)(r * 128 + (g & 7) * 16)),
                       gA + (size_t)r * 2048 + ck * 256 + g * 16);
        }
        #pragma unroll
        for (int k = 0; k < 8; ++k) {       // B: 64 rows x 16 granules
            const int id = tid + k * 128;
            const int r = id >> 4, g = id & 15;
            cp_async16(sb + 8192 + (g >> 3) * 8192 + sw128((uint32_t)(r * 128 + (g & 7) * 16)),
                       gB + (size_t)r * 2048 + ck * 256 + g * 16);
        }
        asm volatile("cp.async.commit_group;" ::: "memory");
    };

    const int wid  = tid >> 5, lane = tid & 31;
    const int wr   = wid >> 1, wc = wid & 1;    // warp tile 16h x 32w
    const int a_row = lane & 15;
    const int a_kb  = (lane >> 4) << 4;
    const int b_row = (((lane >> 4) & 1) << 3) + (lane & 7);
    const int b_kb  = ((lane >> 3) & 1) << 4;

    float acc[4][4];
    #pragma unroll
    for (int nb = 0; nb < 4; ++nb)
        #pragma unroll
        for (int j = 0; j < 4; ++j) acc[nb][j] = 0.f;

    load_chunk(0, 0);
    load_chunk(1, 1);

    #pragma unroll
    for (int ck = 0; ck < 8; ++ck) {
        if (ck < 6) asm volatile("cp.async.wait_group 1;" ::: "memory");
        else        asm volatile("cp.async.wait_group 0;" ::: "memory");
        __syncthreads();

        const uint32_t sb = sbase + (ck % 3) * STAGE_B;
        #pragma unroll
        for (int ks = 0; ks < 8; ++ks) {
            const uint32_t sub   = ks >> 2;
            const uint32_t kbyte = (ks & 3) * 32;

            uint32_t a0, a1, a2, a3;
            ldsm_x4(sb + sub * 4096 +
                        sw128((uint32_t)((wr * 16 + a_row) * 128) + kbyte + a_kb),
                    a0, a1, a2, a3);
            uint32_t b[2][4];
            #pragma unroll
            for (int nb16 = 0; nb16 < 2; ++nb16)
                ldsm_x4(sb + 8192 + sub * 8192 +
                            sw128((uint32_t)((wc * 32 + nb16 * 16 + b_row) * 128) + kbyte + b_kb),
                        b[nb16][0], b[nb16][1], b[nb16][2], b[nb16][3]);
            #pragma unroll
            for (int nb = 0; nb < 4; ++nb)
                mma16816(acc[nb], a0, a1, a2, a3,
                         b[nb >> 1][(nb & 1) ? 2 : 0], b[nb >> 1][(nb & 1) ? 3 : 1]);
        }
        __syncthreads();
        if (ck + 2 < 8) load_chunk(ck + 2, (ck + 2) % 3);
    }

    // direct store of final values (every output written exactly once; no memset)
    const int r  = lane >> 2;
    const int c2 = (lane & 3) * 2;
    float* op = out + (((size_t)n * 3 + c) << 14)
                    + (size_t)(h0 + wr * 16 + r) * 128 + w0 + wc * 32 + c2;
    #pragma unroll
    for (int nb = 0; nb < 4; ++nb) {
        *reinterpret_cast<float2*>(op + nb * 8)           = make_float2(acc[nb][0], acc[nb][1]);
        *reinterpret_cast<float2*>(op + nb * 8 + 8 * 128) = make_float2(acc[nb][2], acc[nb][3]);
    }
}

extern "C" void kernel_launch(void* const* d_in, const int* in_sizes, int n_in,
                              void* d_out, int out_size) {
    const float* coords = (const float*)d_in[0];   // [N,P,2]
    const float* values = (const float*)d_in[1];   // [N,P,C]
    const float* sigma  = (const float*)d_in[2];   // [N,1]

    cudaFuncSetAttribute(splat2d_gemm,
                         cudaFuncAttributeMaxDynamicSharedMemorySize, SMEM2);

    splat2d_tiles<<<512, 256>>>(coords, values, sigma);

    dim3 g2(8, 3, 4);                              // 96 CTAs
    splat2d_gemm<<<g2, 128, SMEM2>>>((float*)d_out);
}

// round 14
// speedup vs baseline: 1.0323x; 1.0323x over previous
#include <cuda_runtime.h>
#include <cuda_fp16.h>
#include <cstdint>
#include <math.h>

// fp16 tile scratch (4MB total): ey[n][h][p], exv[n][c][w][p]
__device__ __half g_ey[4 * 128 * 1024];
__device__ __half g_bv[12 * 128 * 1024];

static __device__ __forceinline__ uint32_t s2u(const void* p) {
    uint32_t a;
    asm("{ .reg .u64 t; cvta.to.shared.u64 t, %1; cvt.u32.u64 %0, t; }" : "=r"(a) : "l"(p));
    return a;
}
static __device__ __forceinline__ float fast_exp2(float x) {
    float y; asm("ex2.approx.ftz.f32 %0, %1;" : "=f"(y) : "f"(x)); return y;
}
static __device__ __forceinline__ uint32_t pack_h2(float lo, float hi) {
    uint32_t u;
    asm("cvt.rn.f16x2.f32 %0, %1, %2;" : "=r"(u) : "f"(hi), "f"(lo));  // d.lo = %2
    return u;
}
static __device__ __forceinline__ uint32_t hmul2(uint32_t a, uint32_t b) {
    uint32_t d;
    asm("mul.rn.f16x2 %0, %1, %2;" : "=r"(d) : "r"(a), "r"(b));
    return d;
}
static __device__ __forceinline__ uint32_t sw128(uint32_t off) {
    return off ^ ((off >> 3) & 0x70);
}
static __device__ __forceinline__ void ldsm_x4(uint32_t addr, uint32_t& r0, uint32_t& r1,
                                               uint32_t& r2, uint32_t& r3) {
    asm volatile("ldmatrix.sync.aligned.m8n8.x4.shared.b16 {%0,%1,%2,%3}, [%4];"
                 : "=r"(r0), "=r"(r1), "=r"(r2), "=r"(r3) : "r"(addr));
}
static __device__ __forceinline__ void ldsm_x2(uint32_t addr, uint32_t& r0, uint32_t& r1) {
    asm volatile("ldmatrix.sync.aligned.m8n8.x2.shared.b16 {%0,%1}, [%2];"
                 : "=r"(r0), "=r"(r1) : "r"(addr));
}
static __device__ __forceinline__ void mma16816(float* c, uint32_t a0, uint32_t a1,
                                                uint32_t a2, uint32_t a3,
                                                uint32_t b0, uint32_t b1) {
    asm volatile(
        "mma.sync.aligned.m16n8k16.row.col.f32.f16.f16.f32 "
        "{%0,%1,%2,%3}, {%4,%5,%6,%7}, {%8,%9}, {%0,%1,%2,%3};"
        : "+f"(c[0]), "+f"(c[1]), "+f"(c[2]), "+f"(c[3])
        : "r"(a0), "r"(a1), "r"(a2), "r"(a3), "r"(b0), "r"(b1));
}
static __device__ __forceinline__ void cp_async16(uint32_t dst, const void* src) {
    asm volatile("cp.async.cg.shared.global [%0], [%1], 16;"
                 :: "r"(dst), "l"(src) : "memory");
}

// ============================================================================
// Phase 1: tile factory (unchanged from R13 — every exp computed exactly once)
// ============================================================================
__global__ void __launch_bounds__(256)
splat2d_tiles(const float* __restrict__ coords,   // [N,1024,2]
              const float* __restrict__ values,   // [N,1024,3]
              const float* __restrict__ sigma) {  // [N,1]
    const int gid   = blockIdx.x * 256 + threadIdx.x;
    const bool isbv = gid < 65536;
    const int t  = isbv ? gid : gid - 65536;
    const int pg = t & 127;                 // 8-point group
    const int rw = (t >> 7) & 127;          // w (bv) or h (ey)
    const int n  = t >> 14;

    const float a_ = sqrtf(0.72134752044448169f) / sigma[n];  // sqrt(log2e/2)/sigma
    const float ar = a_ * (float)rw;

    const float4* cp4 = (const float4*)(coords + (size_t)n * 2048) + pg * 4;
    const float4 q0 = cp4[0], q1 = cp4[1], q2 = cp4[2], q3 = cp4[3];

    if (isbv) {
        const float px[8] = {q0.x, q0.z, q1.x, q1.z, q2.x, q2.z, q3.x, q3.z};
        float e[8];
        #pragma unroll
        for (int i = 0; i < 8; ++i) {
            const float d = fmaf(a_, -px[i], ar);   // a*(w - px)
            e[i] = fast_exp2(-d * d);
        }
        uint32_t eh[4];
        #pragma unroll
        for (int q = 0; q < 4; ++q) eh[q] = pack_h2(e[2 * q], e[2 * q + 1]);

        const float4* vp4 = (const float4*)(values + (size_t)n * 3072 + pg * 24);
        float vf[24];
        #pragma unroll
        for (int j = 0; j < 6; ++j) {
            const float4 v = vp4[j];
            vf[4 * j] = v.x; vf[4 * j + 1] = v.y; vf[4 * j + 2] = v.z; vf[4 * j + 3] = v.w;
        }
        #pragma unroll
        for (int c = 0; c < 3; ++c) {
            uint32_t m[4];
            #pragma unroll
            for (int q = 0; q < 4; ++q)
                m[q] = hmul2(eh[q], pack_h2(vf[6 * q + c], vf[6 * q + 3 + c]));
            ((uint4*)g_bv)[(size_t)((n * 3 + c) * 128 + rw) * 128 + pg] =
                make_uint4(m[0], m[1], m[2], m[3]);
        }
    } else {
        const float py[8] = {q0.y, q0.w, q1.y, q1.w, q2.y, q2.w, q3.y, q3.w};
        float e[8];
        #pragma unroll
        for (int i = 0; i < 8; ++i) {
            const float d = fmaf(a_, -py[i], ar);   // a*(h - py)
            e[i] = fast_exp2(-d * d);
        }
        ((uint4*)g_ey)[(size_t)(n * 128 + rw) * 128 + pg] =
            make_uint4(pack_h2(e[0], e[1]), pack_h2(e[2], e[3]),
                       pack_h2(e[4], e[5]), pack_h2(e[6], e[7]));
    }
}

// ============================================================================
// Phase 2: pure GEMM, K=1024, direct store.
// CTA = (16h x 64w, c, n), grid (16,3,4)=192, block 256 (8 warps, warp 16h x 8w).
// 8 K-chunks of 128p; 3-stage cp.async pipeline; stage = A 4KB + B 16KB = 20KB.
// ============================================================================
#define STAGE_B 20480
#define SMEM2   (3 * STAGE_B)

__global__ void __launch_bounds__(256)
splat2d_gemm(float* __restrict__ out) {
    extern __shared__ __align__(1024) char smem[];
    const uint32_t sbase = s2u(smem);
    const int tid = threadIdx.x;
    const int ht  = blockIdx.x >> 1;        // 16-row h-tile (0..7)
    const int wh  = blockIdx.x & 1;         // 64-col w-half
    const int c   = blockIdx.y;
    const int n   = blockIdx.z;
    const int h0  = ht * 16;
    const int w0  = wh * 64;

    const char* gA = (const char*)g_ey + (size_t)(n * 128 + h0) * 2048;
    const char* gB = (const char*)g_bv + (size_t)((n * 3 + c) * 128 + w0) * 2048;

    auto load_chunk = [&](int ck, int stage) {
        const uint32_t sb = sbase + stage * STAGE_B;
        {   // A: 16 rows x 16 granules = 256 tasks (one per thread)
            const int r = tid >> 4, g = tid & 15;
            cp_async16(sb + (g >> 3) * 2048 + sw128((uint32_t)(r * 128 + (g & 7) * 16)),
                       gA + (size_t)r * 2048 + ck * 256 + g * 16);
        }
        #pragma unroll
        for (int k = 0; k < 4; ++k) {       // B: 64 rows x 16 granules
            const int id = tid + k * 256;
            const int r = id >> 4, g = id & 15;
            cp_async16(sb + 4096 + (g >> 3) * 8192 + sw128((uint32_t)(r * 128 + (g & 7) * 16)),
                       gB + (size_t)r * 2048 + ck * 256 + g * 16);
        }
        asm volatile("cp.async.commit_group;" ::: "memory");
    };

    const int wid  = tid >> 5, lane = tid & 31;
    const int a_row = lane & 15;
    const int a_kb  = (lane >> 4) << 4;
    const int bl    = lane & 15;            // ldsm.x2 uses lanes 0..15 addresses
    const int b_row = wid * 8 + (bl & 7);
    const int b_kb  = ((bl >> 3) & 1) << 4;

    float acc[4] = {0.f, 0.f, 0.f, 0.f};

    load_chunk(0, 0);
    load_chunk(1, 1);

    #pragma unroll
    for (int ck = 0; ck < 8; ++ck) {
        if (ck < 6) asm volatile("cp.async.wait_group 1;" ::: "memory");
        else        asm volatile("cp.async.wait_group 0;" ::: "memory");
        __syncthreads();

        const uint32_t sb = sbase + (ck % 3) * STAGE_B;
        #pragma unroll
        for (int ks = 0; ks < 8; ++ks) {
            const uint32_t sub   = ks >> 2;
            const uint32_t kbyte = (ks & 3) * 32;

            uint32_t a0, a1, a2, a3;
            ldsm_x4(sb + sub * 2048 + sw128((uint32_t)(a_row * 128) + kbyte + a_kb),
                    a0, a1, a2, a3);
            uint32_t b0, b1;
            ldsm_x2(sb + 4096 + sub * 8192 +
                        sw128((uint32_t)(b_row * 128) + kbyte + b_kb),
                    b0, b1);
            mma16816(acc, a0, a1, a2, a3, b0, b1);
        }
        __syncthreads();
        if (ck + 2 < 8) load_chunk(ck + 2, (ck + 2) % 3);
    }

    // direct store of final values (single write per output; no memset)
    const int r  = lane >> 2;
    const int c2 = (lane & 3) * 2;
    float* op = out + (((size_t)n * 3 + c) << 14)
                    + (size_t)(h0 + r) * 128 + w0 + wid * 8 + c2;
    *reinterpret_cast<float2*>(op)           = make_float2(acc[0], acc[1]);
    *reinterpret_cast<float2*>(op + 8 * 128) = make_float2(acc[2], acc[3]);
}

extern "C" void kernel_launch(void* const* d_in, const int* in_sizes, int n_in,
                              void* d_out, int out_size) {
    const float* coords = (const float*)d_in[0];   // [N,P,2]
    const float* values = (const float*)d_in[1];   // [N,P,C]
    const float* sigma  = (const float*)d_in[2];   // [N,1]

    cudaFuncSetAttribute(splat2d_gemm,
                         cudaFuncAttributeMaxDynamicSharedMemorySize, SMEM2);

    splat2d_tiles<<<512, 256>>>(coords, values, sigma);

    dim3 g2(16, 3, 4);                             // 192 CTAs
    splat2d_gemm<<<g2, 256, SMEM2>>>((float*)d_out);
}

// round 15
// speedup vs baseline: 1.2005x; 1.1629x over previous
#include <cuda_runtime.h>
#include <cuda_fp16.h>
#include <cstdint>
#include <math.h>

// fp16 tile scratch (4MB total): ey[n][h][p], exv[n][c][w][p]
__device__ __half g_ey[4 * 128 * 1024];
__device__ __half g_bv[12 * 128 * 1024];

static __device__ __forceinline__ uint32_t s2u(const void* p) {
    uint32_t a;
    asm("{ .reg .u64 t; cvta.to.shared.u64 t, %1; cvt.u32.u64 %0, t; }" : "=r"(a) : "l"(p));
    return a;
}
static __device__ __forceinline__ float fast_exp2(float x) {
    float y; asm("ex2.approx.ftz.f32 %0, %1;" : "=f"(y) : "f"(x)); return y;
}
static __device__ __forceinline__ uint32_t pack_h2(float lo, float hi) {
    uint32_t u;
    asm("cvt.rn.f16x2.f32 %0, %1, %2;" : "=r"(u) : "f"(hi), "f"(lo));  // d.lo = %2
    return u;
}
static __device__ __forceinline__ uint32_t hmul2(uint32_t a, uint32_t b) {
    uint32_t d;
    asm("mul.rn.f16x2 %0, %1, %2;" : "=r"(d) : "r"(a), "r"(b));
    return d;
}
static __device__ __forceinline__ uint32_t sw128(uint32_t off) {
    return off ^ ((off >> 3) & 0x70);
}
static __device__ __forceinline__ void ldsm_x4(uint32_t addr, uint32_t& r0, uint32_t& r1,
                                               uint32_t& r2, uint32_t& r3) {
    asm volatile("ldmatrix.sync.aligned.m8n8.x4.shared.b16 {%0,%1,%2,%3}, [%4];"
                 : "=r"(r0), "=r"(r1), "=r"(r2), "=r"(r3) : "r"(addr));
}
static __device__ __forceinline__ void mma16816(float* c, uint32_t a0, uint32_t a1,
                                                uint32_t a2, uint32_t a3,
                                                uint32_t b0, uint32_t b1) {
    asm volatile(
        "mma.sync.aligned.m16n8k16.row.col.f32.f16.f16.f32 "
        "{%0,%1,%2,%3}, {%4,%5,%6,%7}, {%8,%9}, {%0,%1,%2,%3};"
        : "+f"(c[0]), "+f"(c[1]), "+f"(c[2]), "+f"(c[3])
        : "r"(a0), "r"(a1), "r"(a2), "r"(a3), "r"(b0), "r"(b1));
}
static __device__ __forceinline__ void cp_async16(uint32_t dst, const void* src) {
    asm volatile("cp.async.cg.shared.global [%0], [%1], 16;"
                 :: "r"(dst), "l"(src) : "memory");
}

// ============================================================================
// Phase 1: tile factory (unchanged — every exp computed exactly once)
// ============================================================================
__global__ void __launch_bounds__(256)
splat2d_tiles(const float* __restrict__ coords,   // [N,1024,2]
              const float* __restrict__ values,   // [N,1024,3]
              const float* __restrict__ sigma) {  // [N,1]
    const int gid   = blockIdx.x * 256 + threadIdx.x;
    const bool isbv = gid < 65536;
    const int t  = isbv ? gid : gid - 65536;
    const int pg = t & 127;                 // 8-point group
    const int rw = (t >> 7) & 127;          // w (bv) or h (ey)
    const int n  = t >> 14;

    const float a_ = sqrtf(0.72134752044448169f) / sigma[n];  // sqrt(log2e/2)/sigma
    const float ar = a_ * (float)rw;

    const float4* cp4 = (const float4*)(coords + (size_t)n * 2048) + pg * 4;
    const float4 q0 = cp4[0], q1 = cp4[1], q2 = cp4[2], q3 = cp4[3];

    if (isbv) {
        const float px[8] = {q0.x, q0.z, q1.x, q1.z, q2.x, q2.z, q3.x, q3.z};
        float e[8];
        #pragma unroll
        for (int i = 0; i < 8; ++i) {
            const float d = fmaf(a_, -px[i], ar);   // a*(w - px)
            e[i] = fast_exp2(-d * d);
        }
        uint32_t eh[4];
        #pragma unroll
        for (int q = 0; q < 4; ++q) eh[q] = pack_h2(e[2 * q], e[2 * q + 1]);

        const float4* vp4 = (const float4*)(values + (size_t)n * 3072 + pg * 24);
        float vf[24];
        #pragma unroll
        for (int j = 0; j < 6; ++j) {
            const float4 v = vp4[j];
            vf[4 * j] = v.x; vf[4 * j + 1] = v.y; vf[4 * j + 2] = v.z; vf[4 * j + 3] = v.w;
        }
        #pragma unroll
        for (int c = 0; c < 3; ++c) {
            uint32_t m[4];
            #pragma unroll
            for (int q = 0; q < 4; ++q)
                m[q] = hmul2(eh[q], pack_h2(vf[6 * q + c], vf[6 * q + 3 + c]));
            ((uint4*)g_bv)[(size_t)((n * 3 + c) * 128 + rw) * 128 + pg] =
                make_uint4(m[0], m[1], m[2], m[3]);
        }
    } else {
        const float py[8] = {q0.y, q0.w, q1.y, q1.w, q2.y, q2.w, q3.y, q3.w};
        float e[8];
        #pragma unroll
        for (int i = 0; i < 8; ++i) {
            const float d = fmaf(a_, -py[i], ar);   // a*(h - py)
            e[i] = fast_exp2(-d * d);
        }
        ((uint4*)g_ey)[(size_t)(n * 128 + rw) * 128 + pg] =
            make_uint4(pack_h2(e[0], e[1]), pack_h2(e[2], e[3]),
                       pack_h2(e[4], e[5]), pack_h2(e[6], e[7]));
    }
}

// ============================================================================
// Phase 2: GEMM, K=1024, ALL chunks prefetched up front (192KB smem, no reuse).
// CTA = (32h x 64w, c, n), grid (8,3,4)=96 single wave, block 256 (warp 16h x 16w).
// chunk = 128p: A 8KB (2 x 4KB sub-tiles) + B 16KB (2 x 8KB) = 24KB; 8 chunks.
// ============================================================================
#define CHUNK_B 24576
#define SMEM2   (8 * CHUNK_B)     // 196608 B

__global__ void __launch_bounds__(256)
splat2d_gemm(float* __restrict__ out) {
    extern __shared__ __align__(1024) char smem[];
    const uint32_t sbase = s2u(smem);
    const int tid = threadIdx.x;
    const int ht  = blockIdx.x >> 1;        // 32-row h-tile (0..3)
    const int wh  = blockIdx.x & 1;         // 64-col w-half
    const int c   = blockIdx.y;
    const int n   = blockIdx.z;
    const int h0  = ht * 32;
    const int w0  = wh * 64;

    const char* gA = (const char*)g_ey + (size_t)(n * 128 + h0) * 2048;
    const char* gB = (const char*)g_bv + (size_t)((n * 3 + c) * 128 + w0) * 2048;

    // ---- issue ALL 8 chunks now; one commit group per chunk ----
    #pragma unroll
    for (int ck = 0; ck < 8; ++ck) {
        const uint32_t sb = sbase + ck * CHUNK_B;
        #pragma unroll
        for (int k = 0; k < 2; ++k) {       // A: 32 rows x 16 granules = 512 tasks
            const int id = tid + k * 256;
            const int r = id >> 4, g = id & 15;
            cp_async16(sb + (g >> 3) * 4096 + sw128((uint32_t)(r * 128 + (g & 7) * 16)),
                       gA + (size_t)r * 2048 + ck * 256 + g * 16);
        }
        #pragma unroll
        for (int k = 0; k < 4; ++k) {       // B: 64 rows x 16 granules = 1024 tasks
            const int id = tid + k * 256;
            const int r = id >> 4, g = id & 15;
            cp_async16(sb + 8192 + (g >> 3) * 8192 + sw128((uint32_t)(r * 128 + (g & 7) * 16)),
                       gB + (size_t)r * 2048 + ck * 256 + g * 16);
        }
        asm volatile("cp.async.commit_group;" ::: "memory");
    }

    const int wid  = tid >> 5, lane = tid & 31;
    const int wr   = wid >> 2;              // warp h sub-tile (0..1)
    const int wc   = wid & 3;               // warp w sub-tile (0..3)
    const int a_row = lane & 15;
    const int a_kb  = (lane >> 4) << 4;
    const int b_row = (((lane >> 4) & 1) << 3) + (lane & 7);
    const int b_kb  = ((lane >> 3) & 1) << 4;

    float acc[2][4];
    #pragma unroll
    for (int nb = 0; nb < 2; ++nb)
        #pragma unroll
        for (int j = 0; j < 4; ++j) acc[nb][j] = 0.f;

    // ---- consume chunks in order; latency paid once ----
    #pragma unroll
    for (int ck = 0; ck < 8; ++ck) {
        switch (ck) {   // wait until chunks 0..ck are complete
            case 0: asm volatile("cp.async.wait_group 7;" ::: "memory"); break;
            case 1: asm volatile("cp.async.wait_group 6;" ::: "memory"); break;
            case 2: asm volatile("cp.async.wait_group 5;" ::: "memory"); break;
            case 3: asm volatile("cp.async.wait_group 4;" ::: "memory"); break;
            case 4: asm volatile("cp.async.wait_group 3;" ::: "memory"); break;
            case 5: asm volatile("cp.async.wait_group 2;" ::: "memory"); break;
            case 6: asm volatile("cp.async.wait_group 1;" ::: "memory"); break;
            default: asm volatile("cp.async.wait_group 0;" ::: "memory"); break;
        }
        __syncthreads();

        const uint32_t sb = sbase + ck * CHUNK_B;
        #pragma unroll
        for (int ks = 0; ks < 8; ++ks) {
            const uint32_t sub   = ks >> 2;
            const uint32_t kbyte = (ks & 3) * 32;

            uint32_t a0, a1, a2, a3;
            ldsm_x4(sb + sub * 4096 +
                        sw128((uint32_t)((wr * 16 + a_row) * 128) + kbyte + a_kb),
                    a0, a1, a2, a3);
            uint32_t b0, b1, b2, b3;
            ldsm_x4(sb + 8192 + sub * 8192 +
                        sw128((uint32_t)((wc * 16 + b_row) * 128) + kbyte + b_kb),
                    b0, b1, b2, b3);
            mma16816(acc[0], a0, a1, a2, a3, b0, b1);
            mma16816(acc[1], a0, a1, a2, a3, b2, b3);
        }
        // no trailing barrier: each chunk's smem is written once, read once
    }

    // ---- direct store of final values (single write per output; no memset) ----
    const int r  = lane >> 2;
    const int c2 = (lane & 3) * 2;
    float* op = out + (((size_t)n * 3 + c) << 14)
                    + (size_t)(h0 + wr * 16 + r) * 128 + w0 + wc * 16 + c2;
    #pragma unroll
    for (int nb = 0; nb < 2; ++nb) {
        *reinterpret_cast<float2*>(op + nb * 8)           = make_float2(acc[nb][0], acc[nb][1]);
        *reinterpret_cast<float2*>(op + nb * 8 + 8 * 128) = make_float2(acc[nb][2], acc[nb][3]);
    }
}

extern "C" void kernel_launch(void* const* d_in, const int* in_sizes, int n_in,
                              void* d_out, int out_size) {
    const float* coords = (const float*)d_in[0];   // [N,P,2]
    const float* values = (const float*)d_in[1];   // [N,P,C]
    const float* sigma  = (const float*)d_in[2];   // [N,1]

    cudaFuncSetAttribute(splat2d_gemm,
                         cudaFuncAttributeMaxDynamicSharedMemorySize, SMEM2);

    splat2d_tiles<<<512, 256>>>(coords, values, sigma);

    dim3 g2(8, 3, 4);                              // 96 CTAs, single wave
    splat2d_gemm<<<g2, 256, SMEM2>>>((float*)d_out);
}